// round 15
// baseline (speedup 1.0000x reference)
#include <cuda_runtime.h>

#define G 1024
#define BATCH 4
#define ROWS 24
#define NCHUNK 43              // 42*24=1008, last chunk 15 rows (1023 total)
#define NSTRIP 33              // 33 warps * 31 quads = 1023 columns
#define ROWSTRIDE (G * 3)
#define TOTWARPS (NSTRIP * NCHUNK * BATCH)   // 5676
#define NBLOCKS ((TOTWARPS + 7) / 8)         // 710
#define PF_DIST 9              // prefetch distance in rows

// E = 1023*1023 + 1022*1023 + 1023*1022 = 3,137,541 ; N = B*E
#define N_TOTAL 12550164.0

__device__ double g_acc = 0.0;
__device__ unsigned int g_done = 0;

struct V3 { float x, y, z; };

__device__ __forceinline__ V3 vsub(V3 a, V3 b) {
    V3 r; r.x = a.x - b.x; r.y = a.y - b.y; r.z = a.z - b.z; return r;
}
__device__ __forceinline__ V3 vadd(V3 a, V3 b) {
    V3 r; r.x = a.x + b.x; r.y = a.y + b.y; r.z = a.z + b.z; return r;
}
__device__ __forceinline__ V3 vcross(V3 a, V3 b) {
    V3 r;
    r.x = fmaf(a.y, b.z, -a.z * b.y);
    r.y = fmaf(a.z, b.x, -a.x * b.z);
    r.z = fmaf(a.x, b.y, -a.y * b.x);
    return r;
}
__device__ __forceinline__ float vdot(V3 a, V3 b) {
    return fmaf(a.x, b.x, fmaf(a.y, b.y, a.z * b.z));
}
__device__ __forceinline__ float rq(V3 a) {            // rsqrt(max(|a|^2, eps^2))
    return rsqrtf(fmaxf(vdot(a, a), 1e-16f));
}
__device__ __forceinline__ V3 vscale(V3 a, float s) {
    V3 r; r.x = a.x * s; r.y = a.y * s; r.z = a.z * s; return r;
}
__device__ __forceinline__ V3 ldv(const float* __restrict__ p) {
    V3 r; r.x = p[0]; r.y = p[1]; r.z = p[2]; return r;
}
__device__ __forceinline__ V3 shup(V3 v) {
    V3 r;
    r.x = __shfl_up_sync(0xFFFFFFFFu, v.x, 1);
    r.y = __shfl_up_sync(0xFFFFFFFFu, v.y, 1);
    r.z = __shfl_up_sync(0xFFFFFFFFu, v.z, 1);
    return r;
}
__device__ __forceinline__ void pf_l2(const float* p) {
    asm volatile("prefetch.global.L2 [%0];" :: "l"(p));
}

struct St {
    const float* row;
    V3 p00, p01, u2prev;
    int d3;
    float m_dh, m_v;
};

__device__ __forceinline__ float quad_row(St& s, const float* __restrict__ pfend) {
    const float* __restrict__ nrow = s.row + ROWSTRIDE;
    V3 p10 = ldv(nrow);
    V3 p11 = ldv(nrow + s.d3);

    // zero-cost L2 prefetch of the row PF_DIST ahead (clamped to buffer end)
    const float* pfp = nrow + (PF_DIST - 1) * ROWSTRIDE;
    pf_l2(pfp < pfend ? pfp : pfend - 1);

    V3 e1 = vsub(s.p01, s.p00);
    V3 e2 = vsub(p10,  s.p00);
    V3 dd = vsub(p11,  s.p00);

    V3 cA = vcross(dd, e1);          // T1 normal (tl,br,tr)
    V3 cB = vcross(e2, dd);          // T2 normal (tl,bl,br)
    V3 u1 = vscale(cA, rq(cA));
    V3 u2 = vscale(cB, rq(cB));

    // diag + horiz fused: dot(u1, u2 + u2prev); u2prev==0 on global row 0
    float acc = s.m_dh * vdot(u1, vadd(u2, s.u2prev));
    // vert: left quad's u1 via shuffle
    V3 u1l = shup(u1);
    acc = fmaf(s.m_v, vdot(u2, u1l), acc);

    s.p00 = p10; s.p01 = p11; s.u2prev = u2; s.row = nrow;
    return acc;
}

__global__ void __launch_bounds__(256, 5)
nc_fused_kernel(const float* __restrict__ x, float* __restrict__ out,
                unsigned int nblocks) {
    const int lane = threadIdx.x & 31;
    const int wid  = threadIdx.x >> 5;
    const int W    = blockIdx.x * 8 + wid;

    float sum = 0.0f;
    if (W < TOTWARPS) {
        const int strip = W % NSTRIP;
        const int rest  = W / NSTRIP;
        const int chunk = rest % NCHUNK;
        const int bb    = rest / NCHUNK;

        const int c  = strip * 31 + lane;       // 0..1023
        const int r0 = chunk * ROWS;
        const bool cvalid = (c < G - 1);        // c <= 1022

        St s;
        s.d3   = cvalid ? 3 : 0;                // invalid lane: clamp to own column
        s.m_dh = (lane < 31) ? 1.0f : 0.0f;     // diag+horiz owner lanes
        s.m_v  = (lane >= 1 && cvalid) ? 1.0f : 0.0f;

        const float* __restrict__ base  = x + (size_t)bb * (size_t)G * G * 3;
        const float* __restrict__ pfend = base + (size_t)G * G * 3;
        s.row = base + ((size_t)r0 * G + c) * 3;

        // prologue prefetches: rows r0+1 .. r0+PF_DIST-1 (cover first iterations)
        #pragma unroll
        for (int k = 1; k < PF_DIST; ++k) {
            const float* pfp = s.row + k * ROWSTRIDE;
            pf_l2(pfp < pfend ? pfp : pfend - 1);
        }

        s.p00 = ldv(s.row);
        s.p01 = ldv(s.row + s.d3);
        s.u2prev = V3{0.f, 0.f, 0.f};
        if (r0 >= 1) {                           // û2 of quad (r0-1, c)
            V3 pm = ldv(s.row - ROWSTRIDE);
            V3 e2p = vsub(s.p00, pm);
            V3 dp  = vsub(s.p01, pm);
            V3 cBp = vcross(e2p, dp);
            s.u2prev = vscale(cBp, rq(cBp));
        }

        const int nrows = min(ROWS, (G - 1) - r0);
        if (nrows == ROWS) {
            #pragma unroll 4
            for (int i = 0; i < ROWS; ++i) sum += quad_row(s, pfend);
        } else {
            for (int i = 0; i < nrows; ++i) sum += quad_row(s, pfend);
        }
    }

    // ---- block reduction ----
    #pragma unroll
    for (int off = 16; off > 0; off >>= 1)
        sum += __shfl_down_sync(0xFFFFFFFFu, sum, off);

    __shared__ float warp_sums[8];
    if (lane == 0) warp_sums[wid] = sum;
    __syncthreads();

    __shared__ bool is_last;
    if (wid == 0) {
        float sv = (lane < 8) ? warp_sums[lane] : 0.0f;
        #pragma unroll
        for (int off = 4; off > 0; off >>= 1)
            sv += __shfl_down_sync(0xFFFFFFFFu, sv, off);
        if (lane == 0) {
            atomicAdd(&g_acc, (double)sv);
            __threadfence();
            unsigned int done = atomicInc(&g_done, nblocks - 1);
            is_last = (done == nblocks - 1);
        }
    }
    __syncthreads();

    if (is_last && threadIdx.x == 0) {
        double acc = atomicAdd(&g_acc, 0.0);      // coherent read
        out[0] = (float)(1.0 - acc / N_TOTAL);    // loss = 1 - mean(cos)
        __threadfence();
        g_acc = 0.0;                               // g_done wrapped via atomicInc
    }
}

extern "C" void kernel_launch(void* const* d_in, const int* in_sizes, int n_in,
                              void* d_out, int out_size) {
    const float* x = (const float*)d_in[0];
    float* out = (float*)d_out;

    dim3 block(256, 1, 1);
    dim3 grid(NBLOCKS, 1, 1);   // 710 blocks -> one wave @ 5 CTA/SM
    nc_fused_kernel<<<grid, block>>>(x, out, NBLOCKS);
}

// round 16
// speedup vs baseline: 1.2166x; 1.2166x over previous
#include <cuda_runtime.h>

#define G 1024
#define BATCH 4
#define ROWS 15
#define NCHUNK 69              // 68*15=1020, tail 3 (1023 quad rows)
#define NSTRIP 17              // strips of 62 quad-cols: 17*62=1054 >= 1023
#define ROWSTRIDE (G * 3)
#define TOTWARPS (NSTRIP * NCHUNK * BATCH)   // 4692
#define NBLOCKS ((TOTWARPS + 7) / 8)         // 587 <= 592 (one wave @4 CTA/SM)

// E = 1023*1023 + 1022*1023 + 1023*1022 = 3,137,541 ; N = B*E
#define N_TOTAL 12550164.0

__device__ double g_acc = 0.0;
__device__ unsigned int g_done = 0;

struct V3 { float x, y, z; };

__device__ __forceinline__ V3 vsub(V3 a, V3 b) {
    V3 r; r.x = a.x - b.x; r.y = a.y - b.y; r.z = a.z - b.z; return r;
}
__device__ __forceinline__ V3 vadd(V3 a, V3 b) {
    V3 r; r.x = a.x + b.x; r.y = a.y + b.y; r.z = a.z + b.z; return r;
}
__device__ __forceinline__ V3 vcross(V3 a, V3 b) {
    V3 r;
    r.x = fmaf(a.y, b.z, -a.z * b.y);
    r.y = fmaf(a.z, b.x, -a.x * b.z);
    r.z = fmaf(a.x, b.y, -a.y * b.x);
    return r;
}
__device__ __forceinline__ float vdot(V3 a, V3 b) {
    return fmaf(a.x, b.x, fmaf(a.y, b.y, a.z * b.z));
}
__device__ __forceinline__ float rq(V3 a) {            // rsqrt(max(|a|^2, eps^2))
    return rsqrtf(fmaxf(vdot(a, a), 1e-16f));
}
__device__ __forceinline__ V3 vscale(V3 a, float s) {
    V3 r; r.x = a.x * s; r.y = a.y * s; r.z = a.z * s; return r;
}
__device__ __forceinline__ V3 shup(V3 v) {
    V3 r;
    r.x = __shfl_up_sync(0xFFFFFFFFu, v.x, 1);
    r.y = __shfl_up_sync(0xFFFFFFFFu, v.y, 1);
    r.z = __shfl_up_sync(0xFFFFFFFFu, v.z, 1);
    return r;
}
__device__ __forceinline__ V3 shdn(V3 v) {
    V3 r;
    r.x = __shfl_down_sync(0xFFFFFFFFu, v.x, 1);
    r.y = __shfl_down_sync(0xFFFFFFFFu, v.y, 1);
    r.z = __shfl_down_sync(0xFFFFFFFFu, v.z, 1);
    return r;
}
// load cols (k, k+1) of one vertex row: 6 floats, 8B-aligned -> 3x LDG.64
__device__ __forceinline__ void ldpair(const float* __restrict__ p, V3& v0, V3& v1) {
    float2 l0 = *reinterpret_cast<const float2*>(p);
    float2 l1 = *reinterpret_cast<const float2*>(p + 2);
    float2 l2 = *reinterpret_cast<const float2*>(p + 4);
    v0 = V3{l0.x, l0.y, l1.x};
    v1 = V3{l1.y, l2.x, l2.y};
}

__global__ void __launch_bounds__(256, 4)
nc_fused_kernel(const float* __restrict__ x, float* __restrict__ out,
                unsigned int nblocks) {
    const int lane = threadIdx.x & 31;
    const int wid  = threadIdx.x >> 5;
    const int W    = blockIdx.x * 8 + wid;

    float sum = 0.0f;
    if (W < TOTWARPS) {
        const int strip = W % NSTRIP;
        const int rest  = W / NSTRIP;
        const int chunk = rest % NCHUNK;
        const int bb    = rest / NCHUNK;

        const int c0 = strip * 62;
        const int a  = c0 + 2 * lane;          // 1st owned quad col (even)
        const int b  = a + 1;                  // 2nd owned quad col
        const int cl = min(a, 1022);           // clamped load col (even -> 8B aligned)
        const int r0 = chunk * ROWS;
        const int nrows = min(ROWS, (G - 1) - r0);

        const float mdha = (lane < 31 && a <= 1022) ? 1.0f : 0.0f;
        const float mdhb = (lane < 31 && b <= 1022) ? 1.0f : 0.0f;
        const float mva  = (lane >= 1 && a <= 1022) ? 1.0f : 0.0f;  // vert at even col a
        const float mvb  = mdhb;                                     // vert at odd col b

        const float* __restrict__ row =
            x + (size_t)bb * (size_t)G * G * 3 + ((size_t)r0 * G + cl) * 3;

        V3 va, vb, vc;
        ldpair(row, va, vb);
        vc = shdn(va);                          // col a+2 (lane31: self, masked)

        V3 u2pa = {0.f, 0.f, 0.f}, u2pb = {0.f, 0.f, 0.f};
        if (r0 >= 1) {                          // u2 of quads (r0-1, a) and (r0-1, b)
            V3 pa, pb;
            ldpair(row - ROWSTRIDE, pa, pb);
            V3 cB1 = vcross(vsub(va, pa), vsub(vb, pa));
            V3 cB2 = vcross(vsub(vb, pb), vsub(vc, pb));
            u2pa = vscale(cB1, rq(cB1));
            u2pb = vscale(cB2, rq(cB2));
        }

        const float* __restrict__ rp = row;
        #pragma unroll 3
        for (int i = 0; i < ((nrows == ROWS) ? ROWS : 0); ++i) {
            rp += ROWSTRIDE;
            V3 na, nb;
            ldpair(rp, na, nb);
            V3 nc = shdn(na);

            // quad A (col a)
            V3 cA1 = vcross(vsub(nb, va), vsub(vb, va));
            V3 cB1 = vcross(vsub(na, va), vsub(nb, va));
            V3 u1a = vscale(cA1, rq(cA1));
            V3 u2a = vscale(cB1, rq(cB1));
            sum = fmaf(mdha, vdot(u1a, vadd(u2a, u2pa)), sum);

            // quad B (col b)
            V3 cA2 = vcross(vsub(nc, vb), vsub(vc, vb));
            V3 cB2 = vcross(vsub(nb, vb), vsub(nc, vb));
            V3 u1b = vscale(cA2, rq(cA2));
            V3 u2b = vscale(cB2, rq(cB2));
            sum = fmaf(mdhb, vdot(u1b, vadd(u2b, u2pb)), sum);

            // vertical at odd col b: local (u2b . u1a)
            sum = fmaf(mvb, vdot(u2b, u1a), sum);
            // vertical at even col a: left quad's u1b from lane-1
            V3 u1l = shup(u1b);
            sum = fmaf(mva, vdot(u2a, u1l), sum);

            va = na; vb = nb; vc = nc; u2pa = u2a; u2pb = u2b;
        }
        for (int i = 0; i < ((nrows == ROWS) ? 0 : nrows); ++i) {
            rp += ROWSTRIDE;
            V3 na, nb;
            ldpair(rp, na, nb);
            V3 nc = shdn(na);

            V3 cA1 = vcross(vsub(nb, va), vsub(vb, va));
            V3 cB1 = vcross(vsub(na, va), vsub(nb, va));
            V3 u1a = vscale(cA1, rq(cA1));
            V3 u2a = vscale(cB1, rq(cB1));
            sum = fmaf(mdha, vdot(u1a, vadd(u2a, u2pa)), sum);

            V3 cA2 = vcross(vsub(nc, vb), vsub(vc, vb));
            V3 cB2 = vcross(vsub(nb, vb), vsub(nc, vb));
            V3 u1b = vscale(cA2, rq(cA2));
            V3 u2b = vscale(cB2, rq(cB2));
            sum = fmaf(mdhb, vdot(u1b, vadd(u2b, u2pb)), sum);

            sum = fmaf(mvb, vdot(u2b, u1a), sum);
            V3 u1l = shup(u1b);
            sum = fmaf(mva, vdot(u2a, u1l), sum);

            va = na; vb = nb; vc = nc; u2pa = u2a; u2pb = u2b;
        }
    }

    // ---- block reduction ----
    #pragma unroll
    for (int off = 16; off > 0; off >>= 1)
        sum += __shfl_down_sync(0xFFFFFFFFu, sum, off);

    __shared__ float warp_sums[8];
    if (lane == 0) warp_sums[wid] = sum;
    __syncthreads();

    __shared__ bool is_last;
    if (wid == 0) {
        float sv = (lane < 8) ? warp_sums[lane] : 0.0f;
        #pragma unroll
        for (int off = 4; off > 0; off >>= 1)
            sv += __shfl_down_sync(0xFFFFFFFFu, sv, off);
        if (lane == 0) {
            atomicAdd(&g_acc, (double)sv);
            __threadfence();
            unsigned int done = atomicInc(&g_done, nblocks - 1);
            is_last = (done == nblocks - 1);
        }
    }
    __syncthreads();

    if (is_last && threadIdx.x == 0) {
        double acc = atomicAdd(&g_acc, 0.0);      // coherent read
        out[0] = (float)(1.0 - acc / N_TOTAL);    // loss = 1 - mean(cos)
        __threadfence();
        g_acc = 0.0;                               // g_done wrapped via atomicInc
    }
}

extern "C" void kernel_launch(void* const* d_in, const int* in_sizes, int n_in,
                              void* d_out, int out_size) {
    const float* x = (const float*)d_in[0];
    float* out = (float*)d_out;

    dim3 block(256, 1, 1);
    dim3 grid(NBLOCKS, 1, 1);   // 587 blocks -> one wave @ 4 CTA/SM
    nc_fused_kernel<<<grid, block>>>(x, out, NBLOCKS);
}

// round 17
// speedup vs baseline: 1.2187x; 1.0017x over previous
#include <cuda_runtime.h>

#define G 1024
#define BATCH 4
#define ROWS 20
#define NCHUNK 52              // 51*20=1020, tail chunk 3 rows (1023 total)
#define NSTRIP 17              // strips of 62 quad-cols: 17*62=1054 >= 1023
#define ROWSTRIDE (G * 3)
#define TOTWARPS (NSTRIP * NCHUNK * BATCH)   // 3536
#define NBLOCKS ((TOTWARPS + 7) / 8)         // 442 <= 444 (one wave @3 CTA/SM)

// E = 1023*1023 + 1022*1023 + 1023*1022 = 3,137,541 ; N = B*E
#define N_TOTAL 12550164.0

__device__ double g_acc = 0.0;
__device__ unsigned int g_done = 0;

struct V3 { float x, y, z; };

__device__ __forceinline__ V3 vsub(V3 a, V3 b) {
    V3 r; r.x = a.x - b.x; r.y = a.y - b.y; r.z = a.z - b.z; return r;
}
__device__ __forceinline__ V3 vadd(V3 a, V3 b) {
    V3 r; r.x = a.x + b.x; r.y = a.y + b.y; r.z = a.z + b.z; return r;
}
__device__ __forceinline__ V3 vcross(V3 a, V3 b) {
    V3 r;
    r.x = fmaf(a.y, b.z, -a.z * b.y);
    r.y = fmaf(a.z, b.x, -a.x * b.z);
    r.z = fmaf(a.x, b.y, -a.y * b.x);
    return r;
}
__device__ __forceinline__ float vdot(V3 a, V3 b) {
    return fmaf(a.x, b.x, fmaf(a.y, b.y, a.z * b.z));
}
__device__ __forceinline__ float rq(V3 a) {            // rsqrt(max(|a|^2, eps^2))
    return rsqrtf(fmaxf(vdot(a, a), 1e-16f));
}
__device__ __forceinline__ V3 vscale(V3 a, float s) {
    V3 r; r.x = a.x * s; r.y = a.y * s; r.z = a.z * s; return r;
}
__device__ __forceinline__ V3 shup(V3 v) {
    V3 r;
    r.x = __shfl_up_sync(0xFFFFFFFFu, v.x, 1);
    r.y = __shfl_up_sync(0xFFFFFFFFu, v.y, 1);
    r.z = __shfl_up_sync(0xFFFFFFFFu, v.z, 1);
    return r;
}
__device__ __forceinline__ V3 shdn(V3 v) {
    V3 r;
    r.x = __shfl_down_sync(0xFFFFFFFFu, v.x, 1);
    r.y = __shfl_down_sync(0xFFFFFFFFu, v.y, 1);
    r.z = __shfl_down_sync(0xFFFFFFFFu, v.z, 1);
    return r;
}
// load cols (k, k+1) of one vertex row: 6 floats, 8B-aligned -> 3x LDG.64
__device__ __forceinline__ void ldpair(const float* __restrict__ p, V3& v0, V3& v1) {
    float2 l0 = *reinterpret_cast<const float2*>(p);
    float2 l1 = *reinterpret_cast<const float2*>(p + 2);
    float2 l2 = *reinterpret_cast<const float2*>(p + 4);
    v0 = V3{l0.x, l0.y, l1.x};
    v1 = V3{l1.y, l2.x, l2.y};
}

struct Masks { float mdha, mdhb, mva, mvb; };

// one quad-row: cur row (va,vb,vc) + next row (na,nb,nc); rolls u2pa/u2pb
__device__ __forceinline__ float quads2(
    V3 va, V3 vb, V3 vc, V3 na, V3 nb, V3 nc,
    V3& u2pa, V3& u2pb, const Masks& m)
{
    // quad A (even col)
    V3 cA1 = vcross(vsub(nb, va), vsub(vb, va));
    V3 cB1 = vcross(vsub(na, va), vsub(nb, va));
    V3 u1a = vscale(cA1, rq(cA1));
    V3 u2a = vscale(cB1, rq(cB1));
    float acc = m.mdha * vdot(u1a, vadd(u2a, u2pa));

    // quad B (odd col)
    V3 cA2 = vcross(vsub(nc, vb), vsub(vc, vb));
    V3 cB2 = vcross(vsub(nb, vb), vsub(nc, vb));
    V3 u1b = vscale(cA2, rq(cA2));
    V3 u2b = vscale(cB2, rq(cB2));
    acc = fmaf(m.mdhb, vdot(u1b, vadd(u2b, u2pb)), acc);

    // vertical at odd col: local (u2b . u1a)
    acc = fmaf(m.mvb, vdot(u2b, u1a), acc);
    // vertical at even col: left quad's u1b from lane-1
    V3 u1l = shup(u1b);
    acc = fmaf(m.mva, vdot(u2a, u1l), acc);

    u2pa = u2a; u2pb = u2b;
    return acc;
}

__global__ void __launch_bounds__(256, 3)
nc_fused_kernel(const float* __restrict__ x, float* __restrict__ out,
                unsigned int nblocks) {
    const int lane = threadIdx.x & 31;
    const int wid  = threadIdx.x >> 5;
    const int W    = blockIdx.x * 8 + wid;

    float sum = 0.0f;
    if (W < TOTWARPS) {
        const int strip = W % NSTRIP;
        const int rest  = W / NSTRIP;
        const int chunk = rest % NCHUNK;
        const int bb    = rest / NCHUNK;

        const int c0 = strip * 62;
        const int a  = c0 + 2 * lane;          // 1st owned quad col (even)
        const int b  = a + 1;                  // 2nd owned quad col
        const int cl = min(a, 1022);           // clamped load col (even -> 8B aligned)
        const int r0 = chunk * ROWS;
        const int nrows = min(ROWS, (G - 1) - r0);

        Masks m;
        m.mdha = (lane < 31 && a <= 1022) ? 1.0f : 0.0f;
        m.mdhb = (lane < 31 && b <= 1022) ? 1.0f : 0.0f;
        m.mva  = (lane >= 1 && a <= 1022) ? 1.0f : 0.0f;
        m.mvb  = m.mdhb;

        const float* __restrict__ row =
            x + (size_t)bb * (size_t)G * G * 3 + ((size_t)r0 * G + cl) * 3;

        V3 va, vb, vc;
        ldpair(row, va, vb);
        vc = shdn(va);                          // col a+2 (lane31: self, masked)

        V3 u2pa = {0.f, 0.f, 0.f}, u2pb = {0.f, 0.f, 0.f};
        if (r0 >= 1) {                          // u2 of quads (r0-1, a) and (r0-1, b)
            V3 pa, pb;
            ldpair(row - ROWSTRIDE, pa, pb);
            V3 cB1 = vcross(vsub(va, pa), vsub(vb, pa));
            V3 cB2 = vcross(vsub(vb, pb), vsub(vc, pb));
            u2pa = vscale(cB1, rq(cB1));
            u2pb = vscale(cB2, rq(cB2));
        }

        const float* __restrict__ rp = row;
        if (nrows == ROWS) {
            // full chunk: 2 quad-rows per iteration, both rows' loads issued first
            #pragma unroll 2
            for (int i = 0; i < ROWS / 2; ++i) {
                const float* __restrict__ rp1 = rp + ROWSTRIDE;
                const float* __restrict__ rp2 = rp + 2 * ROWSTRIDE;
                V3 na, nb, ma, mb;
                ldpair(rp1, na, nb);            // row i+1   (3 LDG.64)
                ldpair(rp2, ma, mb);            // row i+2   (3 LDG.64, independent)
                V3 nc = shdn(na);
                V3 mc = shdn(ma);

                sum += quads2(va, vb, vc, na, nb, nc, u2pa, u2pb, m);
                sum += quads2(na, nb, nc, ma, mb, mc, u2pa, u2pb, m);

                va = ma; vb = mb; vc = mc;
                rp = rp2;
            }
        } else {
            // tail chunk (3 rows): single-row loop
            for (int i = 0; i < nrows; ++i) {
                rp += ROWSTRIDE;
                V3 na, nb;
                ldpair(rp, na, nb);
                V3 nc = shdn(na);
                sum += quads2(va, vb, vc, na, nb, nc, u2pa, u2pb, m);
                va = na; vb = nb; vc = nc;
            }
        }
    }

    // ---- block reduction ----
    #pragma unroll
    for (int off = 16; off > 0; off >>= 1)
        sum += __shfl_down_sync(0xFFFFFFFFu, sum, off);

    __shared__ float warp_sums[8];
    if (lane == 0) warp_sums[wid] = sum;
    __syncthreads();

    __shared__ bool is_last;
    if (wid == 0) {
        float sv = (lane < 8) ? warp_sums[lane] : 0.0f;
        #pragma unroll
        for (int off = 4; off > 0; off >>= 1)
            sv += __shfl_down_sync(0xFFFFFFFFu, sv, off);
        if (lane == 0) {
            atomicAdd(&g_acc, (double)sv);
            __threadfence();
            unsigned int done = atomicInc(&g_done, nblocks - 1);
            is_last = (done == nblocks - 1);
        }
    }
    __syncthreads();

    if (is_last && threadIdx.x == 0) {
        double acc = atomicAdd(&g_acc, 0.0);      // coherent read
        out[0] = (float)(1.0 - acc / N_TOTAL);    // loss = 1 - mean(cos)
        __threadfence();
        g_acc = 0.0;                               // g_done wrapped via atomicInc
    }
}

extern "C" void kernel_launch(void* const* d_in, const int* in_sizes, int n_in,
                              void* d_out, int out_size) {
    const float* x = (const float*)d_in[0];
    float* out = (float*)d_out;

    dim3 block(256, 1, 1);
    dim3 grid(NBLOCKS, 1, 1);   // 442 blocks -> one wave @ 3 CTA/SM
    nc_fused_kernel<<<grid, block>>>(x, out, NBLOCKS);
}